// round 5
// baseline (speedup 1.0000x reference)
#include <cuda_runtime.h>
#include <cuda_bf16.h>

// preds: [128, 4096, 50] float32 -> 26,214,400 elems (d_in[0])
// gt:    [128, 4096]     int32   ->    524,288 elems (d_in[1])
// out:   scalar float32
//
// loss = [ LN2*(sum_all log2(1+exp(p)) - sum_{unvoiced} log2(1+exp(p)))
//          - sum_{voiced} p.tgt ] / (50 * n_voiced)
// tgt = 5-tap gaussian blur (reflect) of one_hot(q); support <= 5 bins.
//
// Single persistent kernel, ONE wave (grid = 148 SMs x 7 blocks @ 36 regs).
// Streaming pass first; row-gather second (hits L2: 105MB data < 126MB L2).

#define N_ELEMS   26214400u
#define NF4       6553600u
#define ROWS      524288u
#define NBINS     50

#define SP_BLOCKS  1036          // 148 * 7 -> single wave even at 36 regs
#define SP_THREADS 256
#define NTHREADS   (SP_BLOCKS * SP_THREADS)   // 265216

__device__ float    g_part[SP_BLOCKS];
__device__ int      g_cntp[SP_BLOCKS];
__device__ unsigned g_done;              // ticket; reset by last block

__device__ __forceinline__ float gk(int i) {
    const float K0 = 2.6386456e-4f;
    const float K1 = 0.10645078f;
    const float K2 = 0.78657072f;
    return (i == 2) ? K2 : ((i == 1 || i == 3) ? K1 : K0);
}

__device__ __forceinline__ int quant_q(int g) {
    return (g > 50) ? min((g - 50) / 6, NBINS - 1) : 0;
}

__device__ __forceinline__ float sp2(float p) {   // log2(1 + exp(p))
    return __log2f(1.0f + __expf(p));
}

// prod *= (1 + exp(p))  ==  fma(prod, exp(p), prod)
__device__ __forceinline__ void pmul(float& pr, float p) {
    pr = fmaf(pr, __expf(p), pr);
}

__global__ __launch_bounds__(SP_THREADS) void pitchloss_kernel(
    const float* __restrict__ preds, const int* __restrict__ gt,
    float* __restrict__ out)
{
    const int      tid  = threadIdx.x;
    const unsigned gtid = blockIdx.x * SP_THREADS + tid;

    // ---------------- phase 1: streaming softplus over ALL elements -------
    // log2 of 8-term product: 8x EX2 + 1x LG2 per 8 elements.
    const float4* p4 = reinterpret_cast<const float4*>(preds);
    float acc = 0.0f;
    unsigned i = gtid;
    for (; i + 3u * NTHREADS < NF4; i += 4u * NTHREADS) {
        float4 a = p4[i];
        float4 b = p4[i +      NTHREADS];
        float4 c = p4[i + 2u * NTHREADS];
        float4 d = p4[i + 3u * NTHREADS];
        float pr1 = 1.0f + __expf(a.x);
        pmul(pr1, a.y); pmul(pr1, a.z); pmul(pr1, a.w);
        pmul(pr1, b.x); pmul(pr1, b.y); pmul(pr1, b.z); pmul(pr1, b.w);
        float pr2 = 1.0f + __expf(c.x);
        pmul(pr2, c.y); pmul(pr2, c.z); pmul(pr2, c.w);
        pmul(pr2, d.x); pmul(pr2, d.y); pmul(pr2, d.z); pmul(pr2, d.w);
        acc += __log2f(pr1) + __log2f(pr2);
    }
    for (; i < NF4; i += NTHREADS) {
        float4 a = p4[i];
        float pr = 1.0f + __expf(a.x);
        pmul(pr, a.y); pmul(pr, a.z); pmul(pr, a.w);
        acc += __log2f(pr);
    }

    // ---------------- phase 2: per-row work (mostly L2 hits now) ----------
    float dot = 0.0f, neg = 0.0f;
    int   cnt = 0;
    for (unsigned r = gtid; r < ROWS; r += NTHREADS) {
        int g = gt[r];
        const float* row = preds + (size_t)r * NBINS;
        if (g != 100) {
            cnt++;
            int q = quant_q(g);
            #pragma unroll
            for (int j = -2; j <= 2; j++) {
                int n = q + j;
                if (n < 0 || n > NBINS - 1) continue;
                float t = 0.0f;
                #pragma unroll
                for (int i2 = 0; i2 < 5; i2++) {
                    int m = n + i2 - 2;
                    int mm = (m < 0) ? -m : ((m > NBINS - 1) ? (2*(NBINS-1) - m) : m);
                    if (mm == q) t += gk(i2);
                }
                dot = fmaf(__ldg(row + n), t, dot);
            }
        } else {
            #pragma unroll 5
            for (int n = 0; n < NBINS; n++)
                neg += sp2(__ldg(row + n));
        }
    }

    // ---------------- block reduction -------------------------------------
    const float LN2 = 0.69314718055994530942f;
    float part = fmaf(LN2, acc - neg, -dot);

    __shared__ float sp[SP_THREADS];
    __shared__ int   sc[SP_THREADS];
    sp[tid] = part; sc[tid] = cnt;
    __syncthreads();
    #pragma unroll
    for (int o = SP_THREADS / 2; o > 0; o >>= 1) {
        if (tid < o) { sp[tid] += sp[tid + o]; sc[tid] += sc[tid + o]; }
        __syncthreads();
    }

    __shared__ bool s_last;
    if (tid == 0) {
        g_part[blockIdx.x] = sp[0];
        g_cntp[blockIdx.x] = sc[0];
        __threadfence();
        unsigned t = atomicAdd(&g_done, 1u);
        s_last = (t == SP_BLOCKS - 1);
    }
    __syncthreads();

    // ---------------- last block: deterministic ordered finalize ----------
    if (s_last) {
        float a = 0.0f; int c = 0;
        for (int j = tid; j < SP_BLOCKS; j += SP_THREADS) {
            a += g_part[j]; c += g_cntp[j];
        }
        sp[tid] = a; sc[tid] = c;
        __syncthreads();
        #pragma unroll
        for (int o = SP_THREADS / 2; o > 0; o >>= 1) {
            if (tid < o) { sp[tid] += sp[tid + o]; sc[tid] += sc[tid + o]; }
            __syncthreads();
        }
        if (tid == 0) {
            out[0] = sp[0] / (50.0f * (float)sc[0]);
            g_done = 0;   // reset for next (graph-replayed) launch
        }
    }
}

extern "C" void kernel_launch(void* const* d_in, const int* in_sizes, int n_in,
                              void* d_out, int out_size)
{
    const float* preds = (const float*)d_in[0];
    const int*   gt    = (const int*)d_in[1];
    float* out = (float*)d_out;

    pitchloss_kernel<<<SP_BLOCKS, SP_THREADS>>>(preds, gt, out);
}

// round 6
// speedup vs baseline: 1.5092x; 1.5092x over previous
#include <cuda_runtime.h>
#include <cuda_bf16.h>

// preds: [128, 4096, 50] float32 -> 26,214,400 elems (d_in[0])
// gt:    [128, 4096]     int32   ->    524,288 elems (d_in[1])
// out:   scalar float32
//
// loss = [ LN2*(sum_all log2(1+exp(p)) - sum_{unvoiced} log2(1+exp(p)))
//          - sum_{voiced} p.tgt ] / (50 * n_voiced)
// tgt = 5-tap gaussian blur (reflect) of one_hot(q); support <= 5 bins.
//
// Single fused kernel. __launch_bounds__(256,8) caps regs at 32 so 8 blocks/SM
// (100% occ) -- R3/R5 showed 36 regs -> 7 blocks -> occ 62% -> DRAM collapse.
// Row-gather phase FIRST (R3 ordering, empirically 11us faster than last).

#define N_ELEMS   26214400u
#define NF4       6553600u
#define ROWS      524288u
#define NBINS     50

#define SP_BLOCKS  1184          // 148 * 8, single wave
#define SP_THREADS 256
#define NTHREADS   (SP_BLOCKS * SP_THREADS)   // 303104

__device__ float    g_part[SP_BLOCKS];
__device__ int      g_cntp[SP_BLOCKS];
__device__ unsigned g_done;              // ticket; reset by last block

__device__ __forceinline__ float gk(int i) {
    const float K0 = 2.6386456e-4f;
    const float K1 = 0.10645078f;
    const float K2 = 0.78657072f;
    return (i == 2) ? K2 : ((i == 1 || i == 3) ? K1 : K0);
}

__device__ __forceinline__ int quant_q(int g) {
    return (g > 50) ? min((g - 50) / 6, NBINS - 1) : 0;
}

__device__ __forceinline__ float sp2(float p) {   // log2(1 + exp(p))
    return __log2f(1.0f + __expf(p));
}

// prod *= (1 + exp(p))  ==  fma(prod, exp(p), prod)
__device__ __forceinline__ void pmul(float& pr, float p) {
    pr = fmaf(pr, __expf(p), pr);
}

__global__ __launch_bounds__(SP_THREADS, 8) void pitchloss_kernel(
    const float* __restrict__ preds, const int* __restrict__ gt,
    float* __restrict__ out)
{
    const int      tid  = threadIdx.x;
    const unsigned gtid = blockIdx.x * SP_THREADS + tid;

    // ---------------- phase A: per-row work (voiced dot / unvoiced corr) --
    float dot = 0.0f, neg = 0.0f;
    int   cnt = 0;
    for (unsigned r = gtid; r < ROWS; r += NTHREADS) {
        int g = gt[r];
        const float* row = preds + (size_t)r * NBINS;
        if (g != 100) {
            cnt++;
            int q = quant_q(g);
            #pragma unroll
            for (int j = -2; j <= 2; j++) {
                int n = q + j;
                if (n < 0 || n > NBINS - 1) continue;
                float t = 0.0f;
                #pragma unroll
                for (int i2 = 0; i2 < 5; i2++) {
                    int m = n + i2 - 2;
                    int mm = (m < 0) ? -m : ((m > NBINS - 1) ? (2*(NBINS-1) - m) : m);
                    if (mm == q) t += gk(i2);
                }
                dot = fmaf(__ldg(row + n), t, dot);
            }
        } else {
            #pragma unroll 5
            for (int n = 0; n < NBINS; n++)
                neg += sp2(__ldg(row + n));
        }
    }

    // ---------------- phase B: streaming softplus over ALL elements -------
    // log2 of 8-term product: 8x EX2 + 1x LG2 per 8 elements.
    const float4* p4 = reinterpret_cast<const float4*>(preds);
    float acc = 0.0f;
    unsigned i = gtid;
    for (; i + 3u * NTHREADS < NF4; i += 4u * NTHREADS) {
        float4 a = p4[i];
        float4 b = p4[i +      NTHREADS];
        float4 c = p4[i + 2u * NTHREADS];
        float4 d = p4[i + 3u * NTHREADS];
        float pr1 = 1.0f + __expf(a.x);
        pmul(pr1, a.y); pmul(pr1, a.z); pmul(pr1, a.w);
        pmul(pr1, b.x); pmul(pr1, b.y); pmul(pr1, b.z); pmul(pr1, b.w);
        float pr2 = 1.0f + __expf(c.x);
        pmul(pr2, c.y); pmul(pr2, c.z); pmul(pr2, c.w);
        pmul(pr2, d.x); pmul(pr2, d.y); pmul(pr2, d.z); pmul(pr2, d.w);
        acc += __log2f(pr1) + __log2f(pr2);
    }
    for (; i < NF4; i += NTHREADS) {
        float4 a = p4[i];
        float pr = 1.0f + __expf(a.x);
        pmul(pr, a.y); pmul(pr, a.z); pmul(pr, a.w);
        acc += __log2f(pr);
    }

    // ---------------- block reduction -------------------------------------
    const float LN2 = 0.69314718055994530942f;
    float part = fmaf(LN2, acc - neg, -dot);

    __shared__ float sp[SP_THREADS];
    __shared__ int   sc[SP_THREADS];
    sp[tid] = part; sc[tid] = cnt;
    __syncthreads();
    #pragma unroll
    for (int o = SP_THREADS / 2; o > 0; o >>= 1) {
        if (tid < o) { sp[tid] += sp[tid + o]; sc[tid] += sc[tid + o]; }
        __syncthreads();
    }

    __shared__ bool s_last;
    if (tid == 0) {
        g_part[blockIdx.x] = sp[0];
        g_cntp[blockIdx.x] = sc[0];
        __threadfence();
        unsigned t = atomicAdd(&g_done, 1u);
        s_last = (t == SP_BLOCKS - 1);
    }
    __syncthreads();

    // ---------------- last block: deterministic ordered finalize ----------
    if (s_last) {
        float a = 0.0f; int c = 0;
        for (int j = tid; j < SP_BLOCKS; j += SP_THREADS) {
            a += g_part[j]; c += g_cntp[j];
        }
        sp[tid] = a; sc[tid] = c;
        __syncthreads();
        #pragma unroll
        for (int o = SP_THREADS / 2; o > 0; o >>= 1) {
            if (tid < o) { sp[tid] += sp[tid + o]; sc[tid] += sc[tid + o]; }
            __syncthreads();
        }
        if (tid == 0) {
            out[0] = sp[0] / (50.0f * (float)sc[0]);
            g_done = 0;   // reset for next (graph-replayed) launch
        }
    }
}

extern "C" void kernel_launch(void* const* d_in, const int* in_sizes, int n_in,
                              void* d_out, int out_size)
{
    const float* preds = (const float*)d_in[0];
    const int*   gt    = (const int*)d_in[1];
    float* out = (float*)d_out;

    pitchloss_kernel<<<SP_BLOCKS, SP_THREADS>>>(preds, gt, out);
}